// round 3
// baseline (speedup 1.0000x reference)
#include <cuda_runtime.h>
#include <cooperative_groups.h>
#include <math.h>

namespace cg = cooperative_groups;

#define Mdim 512
#define Ndim 2048
#define Bsz  4
#define Lnum 20
#define CAP  24576            // global nnz cap (E[nnz]=20971)
#define LCAP 6656             // per-CTA (128-row) entry cap
#define ROWCAP 96             // per-row entry cap (E=41, sd=6.3, ~8.7 sigma)
#define MNdim (Mdim*Ndim)
#define EPSV 1e-6f
#define NTH  1024
#define CLSZ 4
#define ROWS_PER_CTA (Mdim/CLSZ)   // 128
#define COLS_PER_CTA (Ndim/CLSZ)   // 512

// ---------------- device scratch ----------------
__device__ int            g_deg[Mdim];
__device__ int            g_rowptr[Mdim + 1];
__device__ int            g_nnz;
__device__ unsigned short g_stage[Mdim * ROWCAP];
__device__ unsigned       g_lin[CAP];
__device__ float          g_wde[Lnum * CAP];
__device__ float          g_mwde[Lnum * CAP];
__device__ float          g_rho[Lnum];

// ---------------- P1: block per row — degree + staged column list ----------------
__global__ void k_prep1(const float4* __restrict__ H4) {
    __shared__ int s_cnt;
    __shared__ unsigned short s_cols[ROWCAP];
    const int i = blockIdx.x;
    if (threadIdx.x == 0) s_cnt = 0;
    __syncthreads();
    const float4* row = H4 + (size_t)i * (Ndim / 4);
    for (int c4 = threadIdx.x; c4 < Ndim / 4; c4 += 256) {
        float4 v = row[c4];
        int cnt = (v.x != 0.0f) + (v.y != 0.0f) + (v.z != 0.0f) + (v.w != 0.0f);
        if (cnt) {
            int base = atomicAdd(&s_cnt, cnt);
            int c = c4 * 4;
            if (v.x != 0.0f && base < ROWCAP) s_cols[base++] = (unsigned short)c;
            if (v.y != 0.0f && base < ROWCAP) s_cols[base++] = (unsigned short)(c + 1);
            if (v.z != 0.0f && base < ROWCAP) s_cols[base++] = (unsigned short)(c + 2);
            if (v.w != 0.0f && base < ROWCAP) s_cols[base++] = (unsigned short)(c + 3);
        }
    }
    __syncthreads();
    int d = min(s_cnt, ROWCAP);
    if (threadIdx.x == 0) g_deg[i] = d;
    for (int k = threadIdx.x; k < d; k += 256)
        g_stage[i * ROWCAP + k] = s_cols[k];
}

// ---------------- P2: scan + expand + softmax + zero out (1 block, 512 th) ----------------
__global__ void k_prep2(const float* __restrict__ rhos, float* __restrict__ out) {
    __shared__ int s[Mdim];
    const int t = threadIdx.x;
    s[t] = g_deg[t];
    __syncthreads();
    for (int off = 1; off < Mdim; off <<= 1) {
        int v = (t >= off) ? s[t - off] : 0;
        __syncthreads();
        s[t] += v;
        __syncthreads();
    }
    g_rowptr[t + 1] = s[t];
    if (t == 0) {
        g_rowptr[0] = 0;
        g_nnz = 0;  // placeholder; set below after sync
    }
    __syncthreads();
    if (t == 0) g_nnz = s[Mdim - 1];
    // expand: thread t owns row t
    int st = s[t] - g_deg[t];
    int d  = g_deg[t];
    unsigned lbase = (unsigned)(t * Ndim);
    for (int k = 0; k < d; k++) {
        int idx = st + k;
        if (idx < CAP) g_lin[idx] = lbase + g_stage[t * ROWCAP + k];
    }
    if (t == 0) {
        *out = 0.0f;
        float mx = -1e30f;
        for (int l = 0; l < Lnum; l++) mx = fmaxf(mx, rhos[l]);
        float e[Lnum], sm = 0.0f;
        for (int l = 0; l < Lnum; l++) { e[l] = expf(rhos[l] - mx); sm += e[l]; }
        float inv = 1.0f / sm;
        for (int l = 0; l < Lnum; l++) g_rho[l] = e[l] * inv;
    }
}

// ---------------- P3: gather dense weights at nonzeros ----------------
__global__ void k_gather(const float* __restrict__ wde, const float* __restrict__ mwde) {
    int nnz = min(g_nnz, CAP);
    int idx = blockIdx.x * blockDim.x + threadIdx.x;
    if (idx >= Lnum * CAP) return;
    int l = idx / CAP;
    int k = idx - l * CAP;
    if (k < nnz) {
        unsigned lin = g_lin[k];
        size_t off = (size_t)l * MNdim + lin;
        g_wde[idx]  = wde[off];
        g_mwde[idx] = mwde[off];
    }
}

// ---------------- main BP recurrence (clustered, 3-phase entry-parallel) ----------------
// floats: msgs LCAP | d LCAP | colA N | colB N | belA N | belB N | sign2 R | rp R |
//         err C | resw L | lacc 16 ; ints: rpt R+1+3 ; u16: lin LCAP ; u8: row LCAP
#define SMEM_BYTES ((2*LCAP + 4*Ndim + 2*ROWS_PER_CTA + COLS_PER_CTA + Lnum + 16 \
                     + (ROWS_PER_CTA + 4)) * 4 + LCAP * 2 + LCAP)

__global__ void __launch_bounds__(NTH, 1) __cluster_dims__(CLSZ, 1, 1)
k_main(const int*   __restrict__ synd,
       const int*   __restrict__ errs,
       const float* __restrict__ llrs,
       const float* __restrict__ wllr,
       const float* __restrict__ mwllr,
       const float* __restrict__ resw,
       float* __restrict__ out)
{
    extern __shared__ char sm_raw[];
    float* s_msgs  = (float*)sm_raw;                 // LCAP
    float* s_d     = s_msgs + LCAP;                  // LCAP
    float* s_colA  = s_d + LCAP;                     // N (16B aligned: 2*6656*4)
    float* s_colB  = s_colA + Ndim;
    float* s_belA  = s_colB + Ndim;
    float* s_belB  = s_belA + Ndim;
    float* s_sign2 = s_belB + Ndim;                  // R (2*sign)
    float* s_rp    = s_sign2 + ROWS_PER_CTA;         // R (row product * off-factor)
    float* s_err   = s_rp + ROWS_PER_CTA;            // C
    float* s_resw  = s_err + COLS_PER_CTA;           // L
    float* s_lacc  = s_resw + Lnum;                  // 16
    int*   s_rpt   = (int*)(s_lacc + 16);            // R+1 (+pad)
    unsigned short* s_lin = (unsigned short*)(s_rpt + ROWS_PER_CTA + 4);  // LCAP
    unsigned char*  s_row = (unsigned char*)(s_lin + LCAP);               // LCAP

    cg::cluster_group cl = cg::this_cluster();
    const int rank = (int)cl.block_rank();
    const int b    = blockIdx.x / CLSZ;
    const int tid  = threadIdx.x;
    const int lane = tid & 31;
    const int wid  = tid >> 5;
    const float OME = 1.0f - EPSV;

    const int r0 = rank * ROWS_PER_CTA;
    const int kbase = g_rowptr[r0];
    int kend = g_rowptr[r0 + ROWS_PER_CTA];
    if (kend - kbase > LCAP) kend = kbase + LCAP;
    const int cnt = kend - kbase;

    // ---- prologue ----
    for (int k = tid; k < cnt; k += NTH) {
        unsigned lin = g_lin[kbase + k];
        s_lin[k]  = (unsigned short)(lin & (Ndim - 1));
        s_row[k]  = (unsigned char)((lin >> 11) - r0);
        s_msgs[k] = 0.0f;
    }
    if (tid <= ROWS_PER_CTA) s_rpt[tid] = g_rowptr[r0 + tid] - kbase;
    if (tid < ROWS_PER_CTA) {
        int row = r0 + tid;
        s_sign2[tid] = 2.0f * (1.0f - 2.0f * (float)synd[b * Mdim + row]);
        // fold the off-support clip factor (1-eps)^(N-deg) into the row product
        int d = g_rowptr[row + 1] - g_rowptr[row];
        s_rp[tid] = powf(OME, (float)(Ndim - d));   // reused as scale each layer
    }
    if (tid < COLS_PER_CTA)
        s_err[tid] = 1.0f - (float)errs[b * Ndim + rank * COLS_PER_CTA + tid];
    if (tid < Lnum) s_resw[tid] = resw[tid];
    for (int j = tid; j < Ndim; j += NTH) {
        s_colA[j] = llrs[j] * wllr[j];     // layer-0 combined column input
        s_colB[j] = 0.0f;
        s_belA[j] = 0.0f;
        s_belB[j] = 0.0f;
    }
    __syncthreads();
    // stash the off-factor per row (s_rp doubles as scratch): copy to registers? keep in
    // a dedicated smem slot instead: reuse top of s_lacc region is too small; simplest:
    __shared__ float s_offf[ROWS_PER_CTA];
    if (tid < ROWS_PER_CTA) s_offf[tid] = s_rp[tid];
    __syncthreads();

    float acc = 0.0f;
    for (int l = 0; l < Lnum; l++) {
        float* colR = (l & 1) ? s_colB : s_colA;   // combined, read
        float* colW = (l & 1) ? s_colA : s_colB;   // partial, accumulate (zeroed)
        float* belW = (l & 1) ? s_belB : s_belA;   // partial, accumulate (zeroed)
        float* belZ = (l & 1) ? s_belA : s_belB;   // zero for next layer
        const float rw = s_resw[l];
        const float* mwde_l = &g_mwde[l * CAP + kbase];
        const float* wde_n  = (l + 1 < Lnum) ? &g_wde[(l + 1) * CAP + kbase] : mwde_l;
        const bool last = (l == Lnum - 1);

        // ---- phase A: entry-parallel tanh ----
        for (int k = tid; k < cnt; k += NTH) {
            float men = colR[s_lin[k]] - s_msgs[k];
            float t = __expf(men);
            float d = __fdividef(t - 1.0f, t + 1.0f);   // tanh(men/2)
            if (d == 0.0f) d = 1.0f;
            d = fminf(fmaxf(d, -OME), OME);
            s_d[k] = d;
        }
        __syncthreads();

        // ---- phase B: warp-per-row product (light) ----
        for (int rr = wid; rr < ROWS_PER_CTA; rr += 32) {
            int st = s_rpt[rr], en = s_rpt[rr + 1];
            float p = 1.0f;
            for (int k = st + lane; k < en; k += 32) p *= s_d[k];
            for (int o = 16; o; o >>= 1) p *= __shfl_xor_sync(0xffffffffu, p, o);
            if (lane == 0) s_rp[rr] = p * s_offf[rr];
        }
        __syncthreads();

        // ---- phase C: entry-parallel update + column atomics ----
        for (int k = tid; k < cnt; k += NTH) {
            float d = s_d[k];
            int i = s_row[k];
            int j = s_lin[k];
            float r = __fdividef(s_rp[i], d);
            float ath = (fabsf(r) < 6.25e-3f) ? r * (1.0f + (1.0f / 3.0f) * r * r)
                                              : atanhf(r);
            float mn = ath * s_sign2[i] + rw * s_msgs[k];
            s_msgs[k] = mn;
            atomicAdd(&belW[j], mn * mwde_l[k]);
            if (!last) atomicAdd(&colW[j], mn * wde_n[k]);
        }
        cl.sync();

        // ---- cluster combine (float4 DSMEM) + overlapped zeroing ----
        if (tid < 128) {
            if (!last) {
                int f4 = rank * 128 + tid;                 // float4 index into N array
                int j = f4 * 4;
                float4 s;
                s.x = llrs[j]     * wllr[(l + 1) * Ndim + j];
                s.y = llrs[j + 1] * wllr[(l + 1) * Ndim + j + 1];
                s.z = llrs[j + 2] * wllr[(l + 1) * Ndim + j + 2];
                s.w = llrs[j + 3] * wllr[(l + 1) * Ndim + j + 3];
                #pragma unroll
                for (int r = 0; r < CLSZ; r++) {
                    float4 p = ((const float4*)cl.map_shared_rank(colW, r))[f4];
                    s.x += p.x; s.y += p.y; s.z += p.z; s.w += p.w;
                }
                #pragma unroll
                for (int r = 0; r < CLSZ; r++)
                    ((float4*)cl.map_shared_rank(colW, r))[f4] = s;
            }
        } else if (tid < 256) {
            int f4 = rank * 128 + (tid - 128);
            int j = f4 * 4;
            float4 x;
            x.x = llrs[j]     * mwllr[l * Ndim + j];
            x.y = llrs[j + 1] * mwllr[l * Ndim + j + 1];
            x.z = llrs[j + 2] * mwllr[l * Ndim + j + 2];
            x.w = llrs[j + 3] * mwllr[l * Ndim + j + 3];
            #pragma unroll
            for (int r = 0; r < CLSZ; r++) {
                float4 p = ((const float4*)cl.map_shared_rank(belW, r))[f4];
                x.x += p.x; x.y += p.y; x.z += p.z; x.w += p.w;
            }
            int jj = (tid - 128) * 4;   // index into owned err slice
            float ls = 0.0f;
            ls += fmaxf(x.x, 0.0f) + log1pf(__expf(-fabsf(x.x))) - s_err[jj]     * x.x;
            ls += fmaxf(x.y, 0.0f) + log1pf(__expf(-fabsf(x.y))) - s_err[jj + 1] * x.y;
            ls += fmaxf(x.z, 0.0f) + log1pf(__expf(-fabsf(x.z))) - s_err[jj + 2] * x.z;
            ls += fmaxf(x.w, 0.0f) + log1pf(__expf(-fabsf(x.w))) - s_err[jj + 3] * x.w;
            acc += g_rho[l] * ls;
        } else {
            // zero local buffers for next layer (colR -> next partial acc; belZ)
            for (int j = tid - 256; j < Ndim; j += NTH - 256) {
                colR[j] = 0.0f;
                belZ[j] = 0.0f;
            }
        }
        cl.sync();
    }

    // ---- loss reduce: acc lives in warps 4..7 ----
    for (int o = 16; o; o >>= 1) acc += __shfl_xor_sync(0xffffffffu, acc, o);
    if (wid >= 4 && wid < 8 && lane == 0) s_lacc[wid - 4] = acc;
    __syncthreads();
    if (tid == 0) {
        float s = s_lacc[0] + s_lacc[1] + s_lacc[2] + s_lacc[3];
        atomicAdd(out, s * (1.0f / (float)Bsz));
    }
}

// ---------------- host launcher ----------------
extern "C" void kernel_launch(void* const* d_in, const int* in_sizes, int n_in,
                              void* d_out, int out_size) {
    const int*   synd  = (const int*)d_in[0];
    const int*   errs  = (const int*)d_in[1];
    const float* H     = (const float*)d_in[2];
    const float* llrs  = (const float*)d_in[3];
    const float* wde   = (const float*)d_in[4];
    const float* wllr  = (const float*)d_in[5];
    const float* mwde  = (const float*)d_in[6];
    const float* mwllr = (const float*)d_in[7];
    const float* rhos  = (const float*)d_in[8];
    const float* resw  = (const float*)d_in[9];
    float* out = (float*)d_out;

    cudaFuncSetAttribute(k_main, cudaFuncAttributeMaxDynamicSharedMemorySize, SMEM_BYTES);

    k_prep1<<<Mdim, 256>>>((const float4*)H);
    k_prep2<<<1, Mdim>>>(rhos, out);
    k_gather<<<(Lnum * CAP + 1023) / 1024, 1024>>>(wde, mwde);
    k_main<<<Bsz * CLSZ, NTH, SMEM_BYTES>>>(synd, errs, llrs, wllr, mwllr, resw, out);
}

// round 4
// speedup vs baseline: 1.0897x; 1.0897x over previous
#include <cuda_runtime.h>
#include <cooperative_groups.h>
#include <math.h>

namespace cg = cooperative_groups;

#define Mdim 512
#define Ndim 2048
#define Bsz  4
#define Lnum 20
#define CAP  24576            // global nnz cap (E[nnz]=20971)
#define LCAP 6656             // per-CTA (128-row) entry cap
#define ROWCAP 96             // per-row entry cap
#define MNdim (Mdim*Ndim)
#define EPSV 1e-6f
#define NTH  1024
#define CLSZ 4
#define ROWS_PER_CTA (Mdim/CLSZ)   // 128
#define COLS_PER_CTA (Ndim/CLSZ)   // 512

// ---------------- device scratch ----------------
__device__ int            g_deg[Mdim];
__device__ int            g_rowptr[Mdim + 1];
__device__ int            g_nnz;
__device__ unsigned short g_stage[Mdim * ROWCAP];
__device__ unsigned       g_lin[CAP];        // CSR (row-major) linear indices
__device__ unsigned short g_perm[CAP];       // CSC pos -> local CSR pos (per 128-row slice)
__device__ int            g_colptr[CLSZ * (Ndim + 1)];
__device__ float          g_wdeC[Lnum * CAP];   // weights_de, CSC order per slice
__device__ float          g_mwdeC[Lnum * CAP];  // marg_weights_de, CSC order per slice
__device__ float          g_rho[Lnum];

// ---------------- P1: block per row — degree + staged column list ----------------
__global__ void k_prep1(const float4* __restrict__ H4) {
    __shared__ int s_cnt;
    __shared__ unsigned short s_cols[ROWCAP];
    const int i = blockIdx.x;
    const int t = threadIdx.x;       // 512 threads, one float4 each
    const int lane = t & 31;
    if (t == 0) s_cnt = 0;
    __syncthreads();
    float4 v = H4[(size_t)i * (Ndim / 4) + t];
    int cnt = (v.x != 0.0f) + (v.y != 0.0f) + (v.z != 0.0f) + (v.w != 0.0f);
    int sc = cnt;
    for (int o = 1; o < 32; o <<= 1) {
        int u = __shfl_up_sync(0xffffffffu, sc, o);
        if (lane >= o) sc += u;
    }
    int total = __shfl_sync(0xffffffffu, sc, 31);
    int base = 0;
    if (lane == 31 && total) base = atomicAdd(&s_cnt, total);
    base = __shfl_sync(0xffffffffu, base, 31);
    int idx = base + sc - cnt;
    int c = t * 4;
    if (v.x != 0.0f && idx < ROWCAP) s_cols[idx++] = (unsigned short)c;
    if (v.y != 0.0f && idx < ROWCAP) s_cols[idx++] = (unsigned short)(c + 1);
    if (v.z != 0.0f && idx < ROWCAP) s_cols[idx++] = (unsigned short)(c + 2);
    if (v.w != 0.0f && idx < ROWCAP) s_cols[idx++] = (unsigned short)(c + 3);
    __syncthreads();
    int d = min(s_cnt, ROWCAP);
    if (t == 0) g_deg[i] = d;
    if (t < d) g_stage[i * ROWCAP + t] = s_cols[t];
}

// ---------------- P2: scan + expand CSR + softmax + zero out (1 block, 512 th) ----------------
__global__ void k_prep2(const float* __restrict__ rhos, float* __restrict__ out) {
    __shared__ int s[Mdim];
    const int t = threadIdx.x;
    s[t] = g_deg[t];
    __syncthreads();
    for (int off = 1; off < Mdim; off <<= 1) {
        int v = (t >= off) ? s[t - off] : 0;
        __syncthreads();
        s[t] += v;
        __syncthreads();
    }
    g_rowptr[t + 1] = s[t];
    if (t == 0) g_rowptr[0] = 0;
    if (t == Mdim - 1) g_nnz = s[Mdim - 1];
    // expand: thread t owns row t
    int st = s[t] - g_deg[t];
    int d  = g_deg[t];
    unsigned lbase = (unsigned)(t * Ndim);
    for (int k = 0; k < d; k++) {
        int idx = st + k;
        if (idx < CAP) g_lin[idx] = lbase + g_stage[t * ROWCAP + k];
    }
    if (t == 0) {
        *out = 0.0f;
        float mx = -1e30f;
        for (int l = 0; l < Lnum; l++) mx = fmaxf(mx, rhos[l]);
        float e[Lnum], sm = 0.0f;
        for (int l = 0; l < Lnum; l++) { e[l] = expf(rhos[l] - mx); sm += e[l]; }
        float inv = 1.0f / sm;
        for (int l = 0; l < Lnum; l++) g_rho[l] = e[l] * inv;
    }
}

// ---------------- P3: per-slice CSC (colptr + perm); grid=CLSZ, 1024 th ----------------
__global__ void k_prep3() {
    __shared__ int s_hist[Ndim];     // counts, then cursors
    __shared__ int s_cp[Ndim + 1];
    __shared__ int s_wsum[32];
    const int blk = blockIdx.x;
    const int t = threadIdx.x;
    const int lane = t & 31;
    const int wid = t >> 5;
    const int kbase = g_rowptr[blk * ROWS_PER_CTA];
    int kend = g_rowptr[(blk + 1) * ROWS_PER_CTA];
    if (kend - kbase > LCAP) kend = kbase + LCAP;
    const int cnt = kend - kbase;

    s_hist[t] = 0; s_hist[t + 1024] = 0;
    __syncthreads();
    for (int k = t; k < cnt; k += 1024)
        atomicAdd(&s_hist[g_lin[kbase + k] & (Ndim - 1)], 1);
    __syncthreads();
    // exclusive scan of 2048 counts: thread t owns elems 2t, 2t+1
    int a = s_hist[2 * t], b = s_hist[2 * t + 1];
    int ssum = a + b;
    int sc = ssum;
    for (int o = 1; o < 32; o <<= 1) {
        int u = __shfl_up_sync(0xffffffffu, sc, o);
        if (lane >= o) sc += u;
    }
    if (lane == 31) s_wsum[wid] = sc;
    __syncthreads();
    if (wid == 0) {
        int v = s_wsum[lane];
        for (int o = 1; o < 32; o <<= 1) {
            int u = __shfl_up_sync(0xffffffffu, v, o);
            if (lane >= o) v += u;
        }
        s_wsum[lane] = v;   // inclusive over warps
    }
    __syncthreads();
    int incl = sc + ((wid > 0) ? s_wsum[wid - 1] : 0);
    int excl = incl - ssum;
    s_cp[2 * t] = excl;
    s_cp[2 * t + 1] = excl + a;
    if (t == 1023) s_cp[Ndim] = incl;
    __syncthreads();
    // cursors = copy of cp
    s_hist[2 * t] = s_cp[2 * t];
    s_hist[2 * t + 1] = s_cp[2 * t + 1];
    g_colptr[blk * (Ndim + 1) + 2 * t]     = s_cp[2 * t];
    g_colptr[blk * (Ndim + 1) + 2 * t + 1] = s_cp[2 * t + 1];
    if (t == 1023) g_colptr[blk * (Ndim + 1) + Ndim] = s_cp[Ndim];
    __syncthreads();
    for (int k = t; k < cnt; k += 1024) {
        int j = g_lin[kbase + k] & (Ndim - 1);
        int pos = atomicAdd(&s_hist[j], 1);
        g_perm[kbase + pos] = (unsigned short)k;
    }
}

// ---------------- P4: gather dense weights at nonzeros, CSC order ----------------
__global__ void k_gather(const float* __restrict__ wde, const float* __restrict__ mwde) {
    int nnz = min(g_nnz, CAP);
    int idx = blockIdx.x * blockDim.x + threadIdx.x;
    if (idx >= Lnum * CAP) return;
    int l = idx / CAP;
    int p = idx - l * CAP;          // global CSC position
    if (p >= nnz) return;
    // find slice
    int blk = 0;
    if (p >= g_rowptr[3 * ROWS_PER_CTA]) blk = 3;
    else if (p >= g_rowptr[2 * ROWS_PER_CTA]) blk = 2;
    else if (p >= g_rowptr[ROWS_PER_CTA]) blk = 1;
    int kbase = g_rowptr[blk * ROWS_PER_CTA];
    unsigned lin = g_lin[kbase + g_perm[p]];
    size_t off = (size_t)l * MNdim + lin;
    g_wdeC[idx]  = wde[off];
    g_mwdeC[idx] = mwde[off];
}

// ---------------- main BP recurrence ----------------
// floats: msgs LCAP | d LCAP | colC N | colP N | belP N | rp R | sign2 R | offf R |
//         err C | resw 32 | rho 32 | lacc 32 ; int rpt R+4 ; u16 lin LCAP, perm LCAP, cptr N+4
#define SMEM_BYTES ((2*LCAP + 3*Ndim + 3*ROWS_PER_CTA + COLS_PER_CTA + 96 \
                     + (ROWS_PER_CTA + 4)) * 4 + (2*LCAP + Ndim + 4) * 2)

__global__ void __launch_bounds__(NTH, 1) __cluster_dims__(CLSZ, 1, 1)
k_main(const int*   __restrict__ synd,
       const int*   __restrict__ errs,
       const float* __restrict__ llrs,
       const float* __restrict__ wllr,
       const float* __restrict__ mwllr,
       const float* __restrict__ resw,
       float* __restrict__ out)
{
    extern __shared__ char sm_raw[];
    float* s_msgs  = (float*)sm_raw;                 // LCAP
    float* s_d     = s_msgs + LCAP;                  // LCAP
    float* s_colC  = s_d + LCAP;                     // N  (combined, read)
    float* s_colP  = s_colC + Ndim;                  // N  (partial, direct store)
    float* s_belP  = s_colP + Ndim;                  // N  (partial, direct store)
    float* s_rp    = s_belP + Ndim;                  // R
    float* s_sign2 = s_rp + ROWS_PER_CTA;            // R
    float* s_offf  = s_sign2 + ROWS_PER_CTA;         // R
    float* s_err   = s_offf + ROWS_PER_CTA;          // C
    float* s_resw  = s_err + COLS_PER_CTA;           // 32
    float* s_rho   = s_resw + 32;                    // 32
    float* s_lacc  = s_rho + 32;                     // 32
    int*   s_rpt   = (int*)(s_lacc + 32);            // R+1 (+pad)
    unsigned short* s_lin  = (unsigned short*)(s_rpt + ROWS_PER_CTA + 4);  // LCAP
    unsigned short* s_perm = s_lin + LCAP;                                  // LCAP
    unsigned short* s_cptr = s_perm + LCAP;                                 // N+1

    cg::cluster_group cl = cg::this_cluster();
    const int rank = (int)cl.block_rank();
    const int b    = blockIdx.x / CLSZ;
    const int tid  = threadIdx.x;
    const int lane = tid & 31;
    const int wid  = tid >> 5;
    const float OME = 1.0f - EPSV;

    const int r0 = rank * ROWS_PER_CTA;
    const int kbase = g_rowptr[r0];
    int kend = g_rowptr[r0 + ROWS_PER_CTA];
    if (kend - kbase > LCAP) kend = kbase + LCAP;
    const int cnt = kend - kbase;

    // ---- prologue ----
    for (int k = tid; k < cnt; k += NTH) {
        s_lin[k]  = (unsigned short)(g_lin[kbase + k] & (Ndim - 1));
        s_perm[k] = g_perm[kbase + k];
        s_msgs[k] = 0.0f;
    }
    for (int j = tid; j <= Ndim; j += NTH)
        s_cptr[j] = (unsigned short)g_colptr[rank * (Ndim + 1) + j];
    if (tid <= ROWS_PER_CTA) s_rpt[tid] = g_rowptr[r0 + tid] - kbase;
    if (tid < ROWS_PER_CTA) {
        int row = r0 + tid;
        s_sign2[tid] = 2.0f * (1.0f - 2.0f * (float)synd[b * Mdim + row]);
        int d = g_rowptr[row + 1] - g_rowptr[row];
        s_offf[tid] = powf(OME, (float)(Ndim - d));
    }
    if (tid < COLS_PER_CTA)
        s_err[tid] = 1.0f - (float)errs[b * Ndim + rank * COLS_PER_CTA + tid];
    if (tid < Lnum) { s_resw[tid] = resw[tid]; s_rho[tid] = g_rho[tid]; }
    for (int j = tid; j < Ndim; j += NTH)
        s_colC[j] = llrs[j] * wllr[j];     // layer-0 combined column input
    __syncthreads();

    float acc = 0.0f;
    for (int l = 0; l < Lnum; l++) {
        const float rw = s_resw[l];
        const bool last = (l == Lnum - 1);
        const float* wmC = &g_mwdeC[l * CAP + kbase];          // CSC order
        const float* wnC = &g_wdeC[(last ? l : l + 1) * CAP + kbase];

        // ---- fused warp-per-row pass: tanh + product + message update ----
        for (int rr = wid; rr < ROWS_PER_CTA; rr += 32) {
            int st = s_rpt[rr], en = s_rpt[rr + 1];
            float p = 1.0f;
            for (int k = st + lane; k < en; k += 32) {
                float msg = s_msgs[k];
                float men = fminf(s_colC[s_lin[k]] - msg, 80.0f);
                float t = __expf(men);
                float d = __fdividef(t - 1.0f, t + 1.0f);   // tanh(men/2)
                if (d == 0.0f) d = 1.0f;
                d = fminf(fmaxf(d, -OME), OME);
                s_d[k] = d;
                p *= d;
            }
            for (int o = 16; o; o >>= 1) p *= __shfl_xor_sync(0xffffffffu, p, o);
            p *= s_offf[rr];
            float sg = s_sign2[rr];
            for (int k = st + lane; k < en; k += 32) {
                float d = s_d[k];
                float r = __fdividef(p, d);
                float ath = (fabsf(r) < 6.25e-3f) ? r * (1.0f + (1.0f / 3.0f) * r * r)
                                                  : atanhf(r);
                s_msgs[k] = ath * sg + rw * s_msgs[k];
            }
        }
        __syncthreads();

        // ---- column-parallel CSC pass: partial col sums + partial beliefs ----
        for (int j = tid; j < Ndim; j += NTH) {
            int st = s_cptr[j], en = s_cptr[j + 1];
            float cs = 0.0f, bs = 0.0f;
            for (int t = st; t < en; t++) {
                float m = s_msgs[s_perm[t]];
                bs += m * wmC[t];
                cs += m * wnC[t];
            }
            s_belP[j] = bs;
            s_colP[j] = cs;
        }
        cl.sync();

        // ---- cluster combine (float4 DSMEM, slice-owned) ----
        if (tid < 128) {
            if (!last) {
                int f4 = rank * 128 + tid;                 // float4 index into N array
                int j = f4 * 4;
                float4 s;
                s.x = llrs[j]     * wllr[(l + 1) * Ndim + j];
                s.y = llrs[j + 1] * wllr[(l + 1) * Ndim + j + 1];
                s.z = llrs[j + 2] * wllr[(l + 1) * Ndim + j + 2];
                s.w = llrs[j + 3] * wllr[(l + 1) * Ndim + j + 3];
                #pragma unroll
                for (int r = 0; r < CLSZ; r++) {
                    float4 p = ((const float4*)cl.map_shared_rank(s_colP, r))[f4];
                    s.x += p.x; s.y += p.y; s.z += p.z; s.w += p.w;
                }
                #pragma unroll
                for (int r = 0; r < CLSZ; r++)
                    ((float4*)cl.map_shared_rank(s_colC, r))[f4] = s;
            }
        } else if (tid < 256) {
            int f4 = rank * 128 + (tid - 128);
            int j = f4 * 4;
            float4 x;
            x.x = llrs[j]     * mwllr[l * Ndim + j];
            x.y = llrs[j + 1] * mwllr[l * Ndim + j + 1];
            x.z = llrs[j + 2] * mwllr[l * Ndim + j + 2];
            x.w = llrs[j + 3] * mwllr[l * Ndim + j + 3];
            #pragma unroll
            for (int r = 0; r < CLSZ; r++) {
                float4 p = ((const float4*)cl.map_shared_rank(s_belP, r))[f4];
                x.x += p.x; x.y += p.y; x.z += p.z; x.w += p.w;
            }
            int jj = (tid - 128) * 4;
            float ls = 0.0f;
            ls += fmaxf(x.x, 0.0f) + log1pf(__expf(-fabsf(x.x))) - s_err[jj]     * x.x;
            ls += fmaxf(x.y, 0.0f) + log1pf(__expf(-fabsf(x.y))) - s_err[jj + 1] * x.y;
            ls += fmaxf(x.z, 0.0f) + log1pf(__expf(-fabsf(x.z))) - s_err[jj + 2] * x.z;
            ls += fmaxf(x.w, 0.0f) + log1pf(__expf(-fabsf(x.w))) - s_err[jj + 3] * x.w;
            acc += s_rho[l] * ls;
        }
        cl.sync();
    }

    // ---- loss reduce: acc lives in warps 4..7 ----
    for (int o = 16; o; o >>= 1) acc += __shfl_xor_sync(0xffffffffu, acc, o);
    if (wid >= 4 && wid < 8 && lane == 0) s_lacc[wid - 4] = acc;
    __syncthreads();
    if (tid == 0) {
        float s = s_lacc[0] + s_lacc[1] + s_lacc[2] + s_lacc[3];
        atomicAdd(out, s * (1.0f / (float)Bsz));
    }
}

// ---------------- host launcher ----------------
extern "C" void kernel_launch(void* const* d_in, const int* in_sizes, int n_in,
                              void* d_out, int out_size) {
    const int*   synd  = (const int*)d_in[0];
    const int*   errs  = (const int*)d_in[1];
    const float* H     = (const float*)d_in[2];
    const float* llrs  = (const float*)d_in[3];
    const float* wde   = (const float*)d_in[4];
    const float* wllr  = (const float*)d_in[5];
    const float* mwde  = (const float*)d_in[6];
    const float* mwllr = (const float*)d_in[7];
    const float* rhos  = (const float*)d_in[8];
    const float* resw  = (const float*)d_in[9];
    float* out = (float*)d_out;

    cudaFuncSetAttribute(k_main, cudaFuncAttributeMaxDynamicSharedMemorySize, SMEM_BYTES);

    k_prep1<<<Mdim, 512>>>((const float4*)H);
    k_prep2<<<1, Mdim>>>(rhos, out);
    k_prep3<<<CLSZ, 1024>>>();
    k_gather<<<(Lnum * CAP + 1023) / 1024, 1024>>>(wde, mwde);
    k_main<<<Bsz * CLSZ, NTH, SMEM_BYTES>>>(synd, errs, llrs, wllr, mwllr, resw, out);
}